// round 5
// baseline (speedup 1.0000x reference)
#include <cuda_runtime.h>
#include <cuda_fp16.h>

#define N_NODES 50000
#define N_EDGES 800000
#define IN_DIM  100
#define OUT_DIM 40
#define CH      25           // 4-feature chunks per row (100/4)
#define SCAN_B  256
#define NSB     196          // ceil(50000/256)
#define NODES_PER_BLK 10     // 250 active threads of 256
#define NPART   128          // stats partial buffers

// ---------------- scratch (device globals) ----------------------------------
__device__ float4 g_B0[N_NODES * CH];          // final H (fp32)
__device__ uint2  g_P[N_NODES * CH];           // fp16 ping
__device__ uint2  g_Q[N_NODES * CH];           // fp16 pong
__device__ float  g_norm[N_NODES];
__device__ int    g_deg[N_NODES];
__device__ int    g_rowptr[N_NODES + 1];
__device__ int    g_pos[N_NODES];
__device__ int    g_esrc[N_EDGES];
__device__ int    g_aggval[NSB];
__device__ int    g_aggflag[NSB];
__device__ int    g_baseval[NSB];
__device__ int    g_baseflag[NSB];
__device__ float  g_psum[NPART][IN_DIM];
__device__ float  g_psq[NPART][IN_DIM];

// ---------------- degree histogram ------------------------------------------
// g_deg is zeroed by k_scanall at the END of the previous run (zero-init on load)
__global__ void k_degree(const int* __restrict__ dst) {
    int i = blockIdx.x * blockDim.x + threadIdx.x;
    if (i < N_EDGES) atomicAdd(&g_deg[dst[i]], 1);
}

// ---------------- single-pass scan + norm + pos + self-reset -----------------
__global__ void k_scanall() {
    int t = threadIdx.x;
    int bid = blockIdx.x;
    int i = bid * SCAN_B + t;
    int d = (i < N_NODES) ? g_deg[i] : 0;
    int lane = t & 31, w = t >> 5;

    // block-local inclusive scan (warp shuffles)
    int x = d;
    #pragma unroll
    for (int off = 1; off < 32; off <<= 1) {
        int y = __shfl_up_sync(0xffffffffu, x, off);
        if (lane >= off) x += y;
    }
    __shared__ int wsum[8];
    if (lane == 31) wsum[w] = x;
    __syncthreads();
    if (w == 0) {
        int s = (lane < 8) ? wsum[lane] : 0;
        #pragma unroll
        for (int off = 1; off < 8; off <<= 1) {
            int y = __shfl_up_sync(0xffffffffu, s, off);
            if (lane >= off) s += y;
        }
        if (lane < 8) wsum[lane] = s;
    }
    __syncthreads();
    int incl_local = x + (w > 0 ? wsum[w - 1] : 0);

    // publish block aggregate
    if (t == SCAN_B - 1) {
        g_aggval[bid] = incl_local;
        __threadfence();
        atomicExch(&g_aggflag[bid], 1);
    }

    __shared__ int s_base;
    __shared__ int wsum2[8];
    if (bid == 0) {
        // gather all aggregates, compute exclusive bases, publish
        int v = 0;
        if (t < NSB) {
            while (atomicAdd(&g_aggflag[t], 0) == 0) __nanosleep(40);
            __threadfence();
            v = g_aggval[t];
        }
        int x2 = v;
        #pragma unroll
        for (int off = 1; off < 32; off <<= 1) {
            int y = __shfl_up_sync(0xffffffffu, x2, off);
            if (lane >= off) x2 += y;
        }
        if (lane == 31) wsum2[w] = x2;
        __syncthreads();
        if (w == 0) {
            int s = (lane < 8) ? wsum2[lane] : 0;
            #pragma unroll
            for (int off = 1; off < 8; off <<= 1) {
                int y = __shfl_up_sync(0xffffffffu, s, off);
                if (lane >= off) s += y;
            }
            if (lane < 8) wsum2[lane] = s;
        }
        __syncthreads();
        int excl = x2 + (w > 0 ? wsum2[w - 1] : 0) - v;
        if (t < NSB) {
            g_baseval[t] = excl;
            __threadfence();
            atomicExch(&g_baseflag[t], 1);
        }
        if (t == 0) s_base = 0;
        __syncthreads();
        // self-reset own flags (aggflag[0] consumed above; baseflag[0] never spun on)
        if (t == 0) { atomicExch(&g_aggflag[0], 0); atomicExch(&g_baseflag[0], 0); }
    } else {
        if (t == 0) {
            while (atomicAdd(&g_baseflag[bid], 0) == 0) __nanosleep(40);
            __threadfence();
            s_base = g_baseval[bid];
            // reset for next replay (both already consumed)
            atomicExch(&g_baseflag[bid], 0);
            atomicExch(&g_aggflag[bid], 0);
        }
        __syncthreads();
    }

    int incl = incl_local + s_base;
    if (i < N_NODES) {
        g_rowptr[i + 1] = incl;
        g_pos[i] = incl - d;
        g_norm[i] = rsqrtf(fmaxf((float)d, 1.0f));
        g_deg[i] = 0;                       // reset for next replay
    }
    if (i == 0) g_rowptr[0] = 0;
}

// ---------------- fused fill + fp16 pre-scale --------------------------------
#define NEB ((N_EDGES + 255) / 256)
__global__ void k_fill_pre(const int* __restrict__ src, const int* __restrict__ dst,
                           const float4* __restrict__ feat) {
    int b = blockIdx.x;
    if (b < NEB) {
        int i = b * 256 + threadIdx.x;
        if (i < N_EDGES) {
            int slot = atomicAdd(&g_pos[dst[i]], 1);
            g_esrc[slot] = src[i];
        }
    } else {
        int i = (b - NEB) * 256 + threadIdx.x;
        if (i < N_NODES * CH) {
            int row = i / CH;
            float n = __ldg(&g_norm[row]);
            float4 f = __ldg(&feat[i]);
            half2 a = __floats2half2_rn(f.x * n, f.y * n);
            half2 c = __floats2half2_rn(f.z * n, f.w * n);
            uint2 o;
            o.x = *(unsigned*)&a;
            o.y = *(unsigned*)&c;
            g_P[i] = o;
        }
    }
}

// ---------------- pull SpMM (fp16 gather, fp32 accumulate) -------------------
// MODE 1: P -> Q (block 0 also zeroes stats partials)
// MODE 2: Q -> P
// MODE 3: P -> g_B0 fp32, + fused column stats into g_psum/g_psq
template <int MODE>
__global__ void k_spmm16() {
    const uint2* __restrict__ in = (MODE == 2) ? g_Q : g_P;

    if (MODE == 1 && blockIdx.x == 0) {
        // zero stats partials for this run (consumed by MODE 3, launched later)
        for (int i = threadIdx.x; i < NPART * IN_DIM; i += blockDim.x) {
            ((float*)g_psum)[i] = 0.f;
            ((float*)g_psq)[i] = 0.f;
        }
    }

    int t = threadIdx.x;
    int local = t / CH;
    int c = t - local * CH;
    int node = blockIdx.x * NODES_PER_BLK + local;
    bool active = (t < NODES_PER_BLK * CH) && (node < N_NODES);

    float ax = 0.f, ay = 0.f, az = 0.f, aw = 0.f;
    float n = 0.f;
    if (active) {
        int beg = __ldg(&g_rowptr[node]);
        int end = __ldg(&g_rowptr[node + 1]);
        int e = beg;
        for (; e + 3 < end; e += 4) {
            int s0 = __ldg(&g_esrc[e]);
            int s1 = __ldg(&g_esrc[e + 1]);
            int s2 = __ldg(&g_esrc[e + 2]);
            int s3 = __ldg(&g_esrc[e + 3]);
            uint2 r0 = __ldg(&in[s0 * CH + c]);
            uint2 r1 = __ldg(&in[s1 * CH + c]);
            uint2 r2 = __ldg(&in[s2 * CH + c]);
            uint2 r3 = __ldg(&in[s3 * CH + c]);
            float2 a0 = __half22float2(*(half2*)&r0.x), b0 = __half22float2(*(half2*)&r0.y);
            float2 a1 = __half22float2(*(half2*)&r1.x), b1 = __half22float2(*(half2*)&r1.y);
            float2 a2 = __half22float2(*(half2*)&r2.x), b2 = __half22float2(*(half2*)&r2.y);
            float2 a3 = __half22float2(*(half2*)&r3.x), b3 = __half22float2(*(half2*)&r3.y);
            ax += (a0.x + a1.x) + (a2.x + a3.x);
            ay += (a0.y + a1.y) + (a2.y + a3.y);
            az += (b0.x + b1.x) + (b2.x + b3.x);
            aw += (b0.y + b1.y) + (b2.y + b3.y);
        }
        for (; e < end; e++) {
            int s = __ldg(&g_esrc[e]);
            uint2 r = __ldg(&in[s * CH + c]);
            float2 a = __half22float2(*(half2*)&r.x);
            float2 b = __half22float2(*(half2*)&r.y);
            ax += a.x; ay += a.y; az += b.x; aw += b.y;
        }
        n = __ldg(&g_norm[node]);
    }

    if (MODE == 3) {
        // final values + fused stats
        float vx = ax * n, vy = ay * n, vz = az * n, vw = aw * n;
        if (active) g_B0[node * CH + c] = make_float4(vx, vy, vz, vw);

        __shared__ float ssum[CH][4];
        __shared__ float ssq[CH][4];
        if (t < CH) {
            #pragma unroll
            for (int k = 0; k < 4; k++) { ssum[t][k] = 0.f; ssq[t][k] = 0.f; }
        }
        __syncthreads();
        if (active) {
            atomicAdd(&ssum[c][0], vx); atomicAdd(&ssum[c][1], vy);
            atomicAdd(&ssum[c][2], vz); atomicAdd(&ssum[c][3], vw);
            atomicAdd(&ssq[c][0], vx * vx); atomicAdd(&ssq[c][1], vy * vy);
            atomicAdd(&ssq[c][2], vz * vz); atomicAdd(&ssq[c][3], vw * vw);
        }
        __syncthreads();
        if (t < CH) {
            int part = blockIdx.x & (NPART - 1);
            #pragma unroll
            for (int k = 0; k < 4; k++) {
                atomicAdd(&g_psum[part][t * 4 + k], ssum[t][k]);
                atomicAdd(&g_psq[part][t * 4 + k], ssq[t][k]);
            }
        }
    } else {
        if (active) {
            float f = n * n;
            half2 h0 = __floats2half2_rn(ax * f, ay * f);
            half2 h1 = __floats2half2_rn(az * f, aw * f);
            uint2 o;
            o.x = *(unsigned*)&h0;
            o.y = *(unsigned*)&h1;
            ((MODE == 1) ? g_Q : g_P)[node * CH + c] = o;
        }
    }
}

// ---------------- fused partial-reduce + fold + GEMM -------------------------
__global__ void k_gemm_fold(const float* __restrict__ W, const float* __restrict__ b,
                            float* __restrict__ out) {
    __shared__ float s_mean[IN_DIM];
    __shared__ float s_istd[IN_DIM];
    __shared__ __align__(16) float s_Wt[IN_DIM * OUT_DIM];
    __shared__ float s_bn[OUT_DIM];
    int t = threadIdx.x;

    if (t < IN_DIM) {
        float s = 0.f, q = 0.f;
        #pragma unroll 8
        for (int p = 0; p < NPART; p++) {
            s += g_psum[p][t];
            q += g_psq[p][t];
        }
        float mean = s / (float)N_NODES;
        float var = (q - (float)N_NODES * mean * mean) / (float)(N_NODES - 1);
        s_mean[t] = mean;
        s_istd[t] = rsqrtf(var);
    }
    __syncthreads();
    for (int i = t; i < IN_DIM * OUT_DIM; i += blockDim.x) {
        int o = i / IN_DIM;
        int f = i - o * IN_DIM;
        s_Wt[f * OUT_DIM + o] = __ldg(&W[i]) * s_istd[f];
    }
    if (t < OUT_DIM) {
        float acc = __ldg(&b[t]);
        for (int f = 0; f < IN_DIM; f++)
            acc -= s_mean[f] * s_istd[f] * __ldg(&W[t * IN_DIM + f]);
        s_bn[t] = acc;
    }
    __syncthreads();

    int row = blockIdx.x * blockDim.x + t;
    if (row >= N_NODES) return;

    float acc[OUT_DIM];
    #pragma unroll
    for (int o = 0; o < OUT_DIM; o++) acc[o] = s_bn[o];

    #pragma unroll
    for (int c = 0; c < CH; c++) {
        float4 h4 = g_B0[row * CH + c];
        #pragma unroll
        for (int k = 0; k < 4; k++) {
            float hv = (k == 0) ? h4.x : (k == 1) ? h4.y : (k == 2) ? h4.z : h4.w;
            const float4* wr = (const float4*)&s_Wt[(c * 4 + k) * OUT_DIM];
            #pragma unroll
            for (int j = 0; j < 10; j++) {
                float4 w = wr[j];
                acc[4 * j + 0] += hv * w.x;
                acc[4 * j + 1] += hv * w.y;
                acc[4 * j + 2] += hv * w.z;
                acc[4 * j + 3] += hv * w.w;
            }
        }
    }
    float4* op = (float4*)(out + (size_t)row * OUT_DIM);
    #pragma unroll
    for (int j = 0; j < 10; j++)
        op[j] = make_float4(acc[4 * j + 0], acc[4 * j + 1], acc[4 * j + 2], acc[4 * j + 3]);
}

// ---------------- launch ------------------------------------------------------

extern "C" void kernel_launch(void* const* d_in, const int* in_sizes, int n_in,
                              void* d_out, int out_size) {
    const float4* feat = (const float4*)d_in[0];   // [N, 100] f32
    const float*  W    = (const float*)d_in[1];    // [40, 100] f32
    const float*  b    = (const float*)d_in[2];    // [40] f32
    const int*    src  = (const int*)d_in[3];      // [E] i32
    const int*    dst  = (const int*)d_in[4];      // [E] i32
    float*        out  = (float*)d_out;            // [N, 40] f32

    const int TB = 256;
    const int n_node_blk  = (N_NODES + TB - 1) / TB;
    const int n_edge_blk  = (N_EDGES + TB - 1) / TB;
    const int n_chunk_blk = (N_NODES * CH + TB - 1) / TB;
    const int n_spmm_blk  = (N_NODES + NODES_PER_BLK - 1) / NODES_PER_BLK;

    k_degree<<<n_edge_blk, TB>>>(dst);
    k_scanall<<<NSB, SCAN_B>>>();
    k_fill_pre<<<n_edge_blk + n_chunk_blk, TB>>>(src, dst, feat);

    k_spmm16<1><<<n_spmm_blk, TB>>>();   // P -> Q (+zero partials)
    k_spmm16<2><<<n_spmm_blk, TB>>>();   // Q -> P
    k_spmm16<3><<<n_spmm_blk, TB>>>();   // P -> B0 (+stats)

    k_gemm_fold<<<n_node_blk, TB>>>(W, b, out);
}